// round 2
// baseline (speedup 1.0000x reference)
#include <cuda_runtime.h>
#include <cuda_fp16.h>
#include <stdint.h>

#define IN_F   4096
#define OUT_F  11008
#define BATCH  16

#define NTILES   (OUT_F / 8)          // 1376 n-tiles of 8 channels
#define K_TASK   1024                 // k-chunk per task
#define K_CHUNKS (IN_F / K_TASK)      // 4
#define NTASKS   (NTILES * K_CHUNKS)  // 5504

#define GEMM_BLOCKS  152
#define GEMM_THREADS 256

#define ROW_H      (IN_F + 8)             // padded row stride in halves (16B pad -> 4-bank shift)
#define SMEM_BYTES (BATCH * ROW_H * 2)    // 131,328 B

__device__ __half  g_xh[BATCH * IN_F];
__device__ unsigned g_ticket;

// ---------------------------------------------------------------------------
// Prologue: x fp32 -> fp16, out = bias (broadcast), reset ticket.
// ---------------------------------------------------------------------------
__global__ void prologue_kernel(const float* __restrict__ x,
                                const float* __restrict__ bias,
                                float* __restrict__ out) {
    int i = blockIdx.x * blockDim.x + threadIdx.x;
    if (i == 0) g_ticket = 0u;
    if (i < BATCH * IN_F) g_xh[i] = __float2half(x[i]);
    const int total  = BATCH * OUT_F;
    const int stride = gridDim.x * blockDim.x;
    for (int j = i; j < total; j += stride) {
        out[j] = __ldg(bias + (j % OUT_F));
    }
}

// ---------------------------------------------------------------------------
// Main GEMM: persistent blocks, warp-level work stealing.
// Task = 8 output channels x 1024 K. Partial result -> scale -> atomicAdd.
// ---------------------------------------------------------------------------
extern __shared__ __half s_x[];

__global__ void __launch_bounds__(GEMM_THREADS, 1)
gemm_kernel(const int* __restrict__ W,
            const float* __restrict__ scale,
            float* __restrict__ out) {
    // ---- Stage x (fp16) into padded smem: row r at halves offset r*ROW_H ----
    {
        const uint4* src = (const uint4*)g_xh;  // 8 halves per uint4
        const int n128 = BATCH * IN_F / 8;      // 8192
        for (int i = threadIdx.x; i < n128; i += blockDim.x) {
            int r = i >> 9;          // 512 uint4 per row
            int c = i & 511;
            *(uint4*)&s_x[r * ROW_H + c * 8] = src[i];
        }
    }
    __syncthreads();

    const int lane = threadIdx.x & 31;
    const int ng   = lane >> 2;   // 0..7 : channel within n-tile (B frag), batch row (A/C frag)
    const int tq   = lane & 3;    // 0..3 : k-quad

    unsigned smem_base = (unsigned)__cvta_generic_to_shared(s_x);
    // ldmatrix x4 per-lane row address offset: row = lane&15, k-half = (lane>>4)
    unsigned a_row_off = (unsigned)((lane & 15) * (ROW_H * 2) + ((lane >> 4) & 1) * 16);

    unsigned t;
    if (lane == 0) t = atomicAdd(&g_ticket, 1u);
    t = __shfl_sync(0xffffffffu, t, 0);

    while (t < NTASKS) {
        const int ntile  = (int)(t % NTILES);
        const int kchunk = (int)(t / NTILES);
        const int ch = ntile * 8;
        const int k0 = kchunk * K_TASK;

        // weight row this thread streams: channel ch+ng; int2 granules
        const int2* wp = (const int2*)(W + (size_t)(ch + ng) * IN_F);

        float c0 = 0.f, c1 = 0.f, c2 = 0.f, c3 = 0.f;

        #pragma unroll 1
        for (int kk = k0; kk < k0 + K_TASK; kk += 128) {   // 8 k16-iters per group
            int2 wlo[8], whi[8];
            #pragma unroll
            for (int i = 0; i < 8; i++) {
                int kb = (kk + i * 16) >> 1;               // int2 index of tile base
                wlo[i] = __ldg(wp + kb + tq);              // k = tq*2, tq*2+1
                whi[i] = __ldg(wp + kb + tq + 4);          // k = tq*2+8, tq*2+9
            }
            #pragma unroll
            for (int i = 0; i < 8; i++) {
                unsigned a0, a1, a2, a3;
                unsigned aaddr = smem_base + a_row_off + (unsigned)((kk + i * 16) * 2);
                asm volatile(
                    "ldmatrix.sync.aligned.m8n8.x4.shared.b16 {%0,%1,%2,%3}, [%4];"
                    : "=r"(a0), "=r"(a1), "=r"(a2), "=r"(a3)
                    : "r"(aaddr));

                __half2 hb0 = __halves2half2(__int2half_rn(wlo[i].x),
                                             __int2half_rn(wlo[i].y));
                __half2 hb1 = __halves2half2(__int2half_rn(whi[i].x),
                                             __int2half_rn(whi[i].y));
                unsigned b0 = *reinterpret_cast<unsigned*>(&hb0);
                unsigned b1 = *reinterpret_cast<unsigned*>(&hb1);

                asm volatile(
                    "mma.sync.aligned.m16n8k16.row.col.f32.f16.f16.f32 "
                    "{%0,%1,%2,%3}, {%4,%5,%6,%7}, {%8,%9}, {%0,%1,%2,%3};"
                    : "+f"(c0), "+f"(c1), "+f"(c2), "+f"(c3)
                    : "r"(a0), "r"(a1), "r"(a2), "r"(a3), "r"(b0), "r"(b1));
            }
        }

        // ---- Epilogue: per-channel scale, accumulate into out ----
        const int  o0 = ch + tq * 2;
        const float s0 = __ldg(scale + o0);
        const float s1 = __ldg(scale + o0 + 1);
        atomicAdd(&out[(size_t)ng * OUT_F + o0],           c0 * s0);
        atomicAdd(&out[(size_t)ng * OUT_F + o0 + 1],       c1 * s1);
        atomicAdd(&out[(size_t)(ng + 8) * OUT_F + o0],     c2 * s0);
        atomicAdd(&out[(size_t)(ng + 8) * OUT_F + o0 + 1], c3 * s1);

        if (lane == 0) t = atomicAdd(&g_ticket, 1u);
        t = __shfl_sync(0xffffffffu, t, 0);
    }
}

// ---------------------------------------------------------------------------
extern "C" void kernel_launch(void* const* d_in, const int* in_sizes, int n_in,
                              void* d_out, int out_size) {
    const float* x     = (const float*)d_in[0];
    const int*   w     = (const int*)  d_in[1];
    const float* scale = (const float*)d_in[2];
    const float* bias  = (const float*)d_in[3];
    float*       out   = (float*)d_out;

    cudaFuncSetAttribute(gemm_kernel,
                         cudaFuncAttributeMaxDynamicSharedMemorySize, SMEM_BYTES);

    prologue_kernel<<<(BATCH * OUT_F + 255) / 256, 256>>>(x, bias, out);
    gemm_kernel<<<GEMM_BLOCKS, GEMM_THREADS, SMEM_BYTES>>>(w, scale, out);
}

// round 3
// speedup vs baseline: 1.2446x; 1.2446x over previous
#include <cuda_runtime.h>
#include <cuda_fp16.h>
#include <stdint.h>

#define IN_F   4096
#define OUT_F  11008
#define BATCH  16

#define NTILES   (OUT_F / 8)            // 1376 n-tiles of 8 channels
#define K_TASK   512                    // k-chunk per task
#define K_CHUNKS (IN_F / K_TASK)        // 8
#define NTASKS   (NTILES * K_CHUNKS)    // 11008

#define GEMM_BLOCKS  152
#define GEMM_THREADS 512                // 16 warps (smem caps us at 1 CTA/SM anyway)

#define ROW_H      (IN_F + 8)           // padded row stride in halves
#define SMEM_BYTES (BATCH * ROW_H * 2)  // 131,328 B

#define KGROUP   128                    // k per pipeline stage (16 LDG.64 per warp)
#define NGROUPS  (K_TASK / KGROUP)      // 4

__device__ __half   g_xh[BATCH * IN_F];
__device__ unsigned g_ticket;

// ---------------------------------------------------------------------------
// Prologue: x fp32 -> fp16, out = bias (broadcast), reset ticket.
// ---------------------------------------------------------------------------
__global__ void prologue_kernel(const float* __restrict__ x,
                                const float* __restrict__ bias,
                                float* __restrict__ out) {
    int i = blockIdx.x * blockDim.x + threadIdx.x;
    if (i == 0) g_ticket = 0u;
    if (i < BATCH * IN_F) g_xh[i] = __float2half(x[i]);
    const int total  = BATCH * OUT_F;
    const int stride = gridDim.x * blockDim.x;
    for (int j = i; j < total; j += stride) {
        out[j] = __ldg(bias + (j % OUT_F));
    }
}

// ---------------------------------------------------------------------------
// Main GEMM: persistent blocks, warp-level work stealing, double-buffered
// weight prefetch. Task = 8 output channels x 512 K.
// ---------------------------------------------------------------------------
extern __shared__ __half s_x[];

__global__ void __launch_bounds__(GEMM_THREADS, 1)
gemm_kernel(const int* __restrict__ W,
            const float* __restrict__ scale,
            float* __restrict__ out) {
    // ---- Stage x (fp16) into padded smem ----
    {
        const uint4* src = (const uint4*)g_xh;   // 8 halves per uint4
        const int n128 = BATCH * IN_F / 8;       // 8192
        for (int i = threadIdx.x; i < n128; i += blockDim.x) {
            int r = i >> 9;                      // 512 uint4 per row
            int c = i & 511;
            *(uint4*)&s_x[r * ROW_H + c * 8] = src[i];
        }
    }
    __syncthreads();

    const int lane = threadIdx.x & 31;
    const int ng   = lane >> 2;   // 0..7 : weight row within n-tile
    const int tq   = lane & 3;    // 0..3 : k-quad

    unsigned smem_base = (unsigned)__cvta_generic_to_shared(s_x);
    unsigned a_row_off = (unsigned)((lane & 15) * (ROW_H * 2) + ((lane >> 4) & 1) * 16);

    unsigned t;
    if (lane == 0) t = atomicAdd(&g_ticket, 1u);
    t = __shfl_sync(0xffffffffu, t, 0);

    while (t < NTASKS) {
        // Grab next ticket immediately -> ATOMG latency hidden under this task.
        unsigned tn;
        if (lane == 0) tn = atomicAdd(&g_ticket, 1u);

        const int ntile  = (int)(t % NTILES);
        const int kchunk = (int)(t / NTILES);
        const int ch = ntile * 8;
        const int k0 = kchunk * K_TASK;

        const int2* wp = (const int2*)(W + (size_t)(ch + ng) * IN_F);

        float c0 = 0.f, c1 = 0.f, c2 = 0.f, c3 = 0.f;

        int2 wlo[2][8], whi[2][8];

        // Prime stage 0
        #pragma unroll
        for (int i = 0; i < 8; i++) {
            int kb = (k0 + i * 16) >> 1;
            wlo[0][i] = __ldg(wp + kb + tq);
            whi[0][i] = __ldg(wp + kb + tq + 4);
        }

        #pragma unroll
        for (int g = 0; g < NGROUPS; g++) {
            const int cur = g & 1;
            const int nxt = cur ^ 1;
            const int kk  = k0 + g * KGROUP;

            // Prefetch next group while current group computes.
            if (g + 1 < NGROUPS) {
                #pragma unroll
                for (int i = 0; i < 8; i++) {
                    int kb = (kk + KGROUP + i * 16) >> 1;
                    wlo[nxt][i] = __ldg(wp + kb + tq);
                    whi[nxt][i] = __ldg(wp + kb + tq + 4);
                }
            }

            #pragma unroll
            for (int i = 0; i < 8; i++) {
                unsigned a0, a1, a2, a3;
                unsigned aaddr = smem_base + a_row_off + (unsigned)((kk + i * 16) * 2);
                asm volatile(
                    "ldmatrix.sync.aligned.m8n8.x4.shared.b16 {%0,%1,%2,%3}, [%4];"
                    : "=r"(a0), "=r"(a1), "=r"(a2), "=r"(a3)
                    : "r"(aaddr));

                __half2 hb0 = __halves2half2(__int2half_rn(wlo[cur][i].x),
                                             __int2half_rn(wlo[cur][i].y));
                __half2 hb1 = __halves2half2(__int2half_rn(whi[cur][i].x),
                                             __int2half_rn(whi[cur][i].y));
                unsigned b0 = *reinterpret_cast<unsigned*>(&hb0);
                unsigned b1 = *reinterpret_cast<unsigned*>(&hb1);

                asm volatile(
                    "mma.sync.aligned.m16n8k16.row.col.f32.f16.f16.f32 "
                    "{%0,%1,%2,%3}, {%4,%5,%6,%7}, {%8,%9}, {%0,%1,%2,%3};"
                    : "+f"(c0), "+f"(c1), "+f"(c2), "+f"(c3)
                    : "r"(a0), "r"(a1), "r"(a2), "r"(a3), "r"(b0), "r"(b1));
            }
        }

        // ---- Epilogue: per-channel scale, accumulate into out ----
        const int  o0 = ch + tq * 2;
        const float s0 = __ldg(scale + o0);
        const float s1 = __ldg(scale + o0 + 1);
        atomicAdd(&out[(size_t)ng * OUT_F + o0],           c0 * s0);
        atomicAdd(&out[(size_t)ng * OUT_F + o0 + 1],       c1 * s1);
        atomicAdd(&out[(size_t)(ng + 8) * OUT_F + o0],     c2 * s0);
        atomicAdd(&out[(size_t)(ng + 8) * OUT_F + o0 + 1], c3 * s1);

        t = __shfl_sync(0xffffffffu, tn, 0);
    }
}

// ---------------------------------------------------------------------------
extern "C" void kernel_launch(void* const* d_in, const int* in_sizes, int n_in,
                              void* d_out, int out_size) {
    const float* x     = (const float*)d_in[0];
    const int*   w     = (const int*)  d_in[1];
    const float* scale = (const float*)d_in[2];
    const float* bias  = (const float*)d_in[3];
    float*       out   = (float*)d_out;

    cudaFuncSetAttribute(gemm_kernel,
                         cudaFuncAttributeMaxDynamicSharedMemorySize, SMEM_BYTES);

    prologue_kernel<<<(BATCH * OUT_F + 255) / 256, 256>>>(x, bias, out);
    gemm_kernel<<<GEMM_BLOCKS, GEMM_THREADS, SMEM_BYTES>>>(w, scale, out);
}